// round 2
// baseline (speedup 1.0000x reference)
#include <cuda_runtime.h>

#define BB 16
#define NN 16384
#define CC 128
#define KK 9
#define FF (KK*CC)   // 1152
#define TM 32
#define THREADS 256

// Pre-transposed weights, interleaved [f>>2][o][f&3] so the GEMM phase does a
// single coalesced LDG.128 per thread per 4-feature chunk.
__device__ float g_WtC[FF * CC];   // 589,824 B
__device__ float g_WtS[CC * CC];   // 65,536 B

__global__ void transpose_w_kernel(const float* __restrict__ Wc,
                                   const float* __restrict__ Ws) {
    int tid = blockIdx.x * blockDim.x + threadIdx.x;
    if (tid < FF * CC) {
        int q  = tid & 3;
        int o  = (tid >> 2) & (CC - 1);
        int fq = tid >> 9;
        int f  = fq * 4 + q;
        g_WtC[tid] = Wc[o * FF + f];
    }
    if (tid < CC * CC) {
        int q  = tid & 3;
        int o  = (tid >> 2) & (CC - 1);
        int cq = tid >> 9;
        int c  = cq * 4 + q;
        g_WtS[tid] = Ws[o * CC + c];
    }
}

// smem layout: flat[TM][FF] | x[TM][CC] | P[TM][81] | idx[TM][9]
#define SMEM_FLOATS (TM*FF + TM*CC + TM*KK*KK + TM*KK)
#define SMEM_BYTES  (SMEM_FLOATS * 4)

__global__ __launch_bounds__(THREADS, 1)
void paiconv_kernel(const float* __restrict__ x,
                    const int*   __restrict__ indices,
                    const float* __restrict__ P,
                    const float* __restrict__ b_conv,
                    const float* __restrict__ b_skip,
                    float*       __restrict__ out)
{
    extern __shared__ float smem[];
    float* s_flat = smem;                      // TM*FF
    float* s_x    = s_flat + TM * FF;          // TM*CC
    float* s_P    = s_x + TM * CC;             // TM*81
    int*   s_idx  = (int*)(s_P + TM * KK * KK);// TM*9

    const int n0  = blockIdx.x * TM;
    const int b   = blockIdx.y;
    const int tid = threadIdx.x;

    // Stage indices + P tiles (contiguous in global)
    for (int t = tid; t < TM * KK; t += THREADS)
        s_idx[t] = indices[n0 * KK + t];
    for (int t = tid; t < TM * KK * KK; t += THREADS)
        s_P[t] = P[(size_t)n0 * KK * KK + t];
    __syncthreads();

    const float* xb = x + (size_t)b * NN * CC;

    // ---------------- Phase A: gather + 9x9 mix + ELU -> s_flat ----------------
    {
        const int c    = tid & (CC - 1);
        const int half = tid >> 7;             // 0 or 1
        for (int tm = half; tm < TM; tm += 2) {
            const int n = n0 + tm;
            float v[KK];
            #pragma unroll
            for (int j = 0; j < KK; j++) {
                unsigned ix = (unsigned)s_idx[tm * KK + j];
                v[j] = (ix < (unsigned)NN) ? xb[(size_t)ix * CC + c] : 0.0f;
            }
            const float* Pn = s_P + tm * KK * KK;
            float* fl = s_flat + (size_t)tm * FF + c;
            #pragma unroll
            for (int k = 0; k < KK; k++) {
                float p = 0.0f;
                #pragma unroll
                for (int j = 0; j < KK; j++)
                    p = fmaf(Pn[k * KK + j], v[j], p);
                p = (p > 0.0f) ? p : (__expf(p) - 1.0f);   // ELU
                fl[k * CC] = p;
            }
            s_x[tm * CC + c] = xb[(size_t)n * CC + c];
        }
    }
    __syncthreads();

    // ---------------- Phase B: conv GEMM + ELU + skip ----------------
    const int o  = tid & (CC - 1);
    const int mh = tid >> 7;                   // which 16-node half

    float acc[16];
    #pragma unroll
    for (int i = 0; i < 16; i++) acc[i] = 0.0f;

    const float4* __restrict__ WtC = (const float4*)g_WtC;
    const float*  fl_base = s_flat + (size_t)mh * 16 * FF;

    #pragma unroll 2
    for (int f0 = 0; f0 < FF; f0 += 4) {
        const float4 w = WtC[(size_t)(f0 >> 2) * CC + o];
        #pragma unroll
        for (int i = 0; i < 16; i++) {
            const float4 a = *(const float4*)(fl_base + (size_t)i * FF + f0);
            float s = acc[i];
            s = fmaf(w.x, a.x, s);
            s = fmaf(w.y, a.y, s);
            s = fmaf(w.z, a.z, s);
            s = fmaf(w.w, a.w, s);
            acc[i] = s;
        }
    }

    float acc2[16];
    #pragma unroll
    for (int i = 0; i < 16; i++) acc2[i] = 0.0f;

    const float4* __restrict__ WtS = (const float4*)g_WtS;
    const float*  xs_base = s_x + (size_t)mh * 16 * CC;

    #pragma unroll 4
    for (int c0 = 0; c0 < CC; c0 += 4) {
        const float4 w = WtS[(size_t)(c0 >> 2) * CC + o];
        #pragma unroll
        for (int i = 0; i < 16; i++) {
            const float4 a = *(const float4*)(xs_base + (size_t)i * CC + c0);
            float s = acc2[i];
            s = fmaf(w.x, a.x, s);
            s = fmaf(w.y, a.y, s);
            s = fmaf(w.z, a.z, s);
            s = fmaf(w.w, a.w, s);
            acc2[i] = s;
        }
    }

    const float bc = b_conv[o];
    const float bs = b_skip[o];
    float* outb = out + ((size_t)b * NN + n0 + mh * 16) * CC + o;
    #pragma unroll
    for (int i = 0; i < 16; i++) {
        float zc = acc[i] + bc;
        zc = (zc > 0.0f) ? zc : (__expf(zc) - 1.0f);       // ELU
        outb[(size_t)i * CC] = zc + acc2[i] + bs;
    }
}

extern "C" void kernel_launch(void* const* d_in, const int* in_sizes, int n_in,
                              void* d_out, int out_size) {
    const float* x       = (const float*)d_in[0];
    const int*   indices = (const int*)  d_in[1];
    const float* P       = (const float*)d_in[2];
    const float* W_conv  = (const float*)d_in[3];
    const float* b_conv  = (const float*)d_in[4];
    const float* W_skip  = (const float*)d_in[5];
    const float* b_skip  = (const float*)d_in[6];
    float* out = (float*)d_out;

    transpose_w_kernel<<<(FF * CC + 255) / 256, 256>>>(W_conv, W_skip);

    cudaFuncSetAttribute(paiconv_kernel,
                         cudaFuncAttributeMaxDynamicSharedMemorySize, SMEM_BYTES);
    dim3 grid(NN / TM, BB);
    paiconv_kernel<<<grid, THREADS, SMEM_BYTES>>>(x, indices, P,
                                                  b_conv, b_skip, out);
}

// round 4
// speedup vs baseline: 4.4042x; 4.4042x over previous
#include <cuda_runtime.h>
#include <cuda_fp16.h>
#include <cstdint>

#define BB 16
#define NN 16384
#define CC 128
#define KK 9
#define TM 64
#define THREADS 512

#define FLAT_STRIDE_B 2320      // 1160 halfs per row (1152 + 8 pad)
#define XS_STRIDE_B   272       // 136 halfs per row (128 + 8 pad)
#define W_ROW_B       144       // 64 halfs + 8 pad
#define WBUF_STAGE_B  (128 * W_ROW_B)   // 18432
#define W_STAGE_GB    (128 * 64 * 2)    // 16384 bytes per stage in global

// smem layout (bytes)
#define FLAT_OFF 0
#define W_OFF    (TM * FLAT_STRIDE_B)           // 148480
#define P_OFF    (W_OFF + 2 * WBUF_STAGE_B)     // 185344
#define IDX_OFF  (P_OFF + TM * 84 * 4)          // 206848
#define BIAS_OFF (IDX_OFF + TM * KK * 4)        // 209152
#define SMEM_TOTAL (BIAS_OFF + 256 * 4)         // 210176

// fp16 pre-transposed weights: [stage][o(128)][k(64)]
__device__ __align__(16) __half g_Wc2[18 * 128 * 64];
__device__ __align__(16) __half g_Ws2[2 * 128 * 64];

__global__ void prep_w(const float* __restrict__ Wc, const float* __restrict__ Ws) {
    int t = blockIdx.x * blockDim.x + threadIdx.x;
    if (t < 18 * 128 * 64) {
        int s = t >> 13, r = t & 8191, n = r >> 6, kk = r & 63;
        g_Wc2[t] = __float2half_rn(Wc[n * 1152 + s * 64 + kk]);
    }
    if (t < 2 * 128 * 64) {
        int s = t >> 13, r = t & 8191, n = r >> 6, kk = r & 63;
        g_Ws2[t] = __float2half_rn(Ws[n * 128 + s * 64 + kk]);
    }
}

// ---------------- PTX helpers (baseline ISA only) ----------------
__device__ __forceinline__ uint32_t smem_u32(const void* p) {
    uint32_t a;
    asm("{ .reg .u64 t; cvta.to.shared.u64 t, %1; cvt.u32.u64 %0, t; }" : "=r"(a) : "l"(p));
    return a;
}
#define CP_ASYNC16(dst, src) \
    asm volatile("cp.async.cg.shared.global [%0], [%1], 16;" :: "r"(dst), "l"(src))
#define CP_COMMIT() asm volatile("cp.async.commit_group;" ::: "memory")
#define CP_WAIT(n)  asm volatile("cp.async.wait_group %0;" :: "n"(n) : "memory")

__device__ __forceinline__ void ldsm_x4(uint32_t* r, uint32_t addr) {
    asm volatile("ldmatrix.sync.aligned.m8n8.x4.shared.b16 {%0,%1,%2,%3}, [%4];"
                 : "=r"(r[0]), "=r"(r[1]), "=r"(r[2]), "=r"(r[3]) : "r"(addr));
}
__device__ __forceinline__ void mma16816(float* c, const uint32_t* a,
                                         uint32_t b0, uint32_t b1) {
    asm volatile("mma.sync.aligned.m16n8k16.row.col.f32.f16.f16.f32 "
                 "{%0,%1,%2,%3}, {%4,%5,%6,%7}, {%8,%9}, {%0,%1,%2,%3};"
                 : "+f"(c[0]), "+f"(c[1]), "+f"(c[2]), "+f"(c[3])
                 : "r"(a[0]), "r"(a[1]), "r"(a[2]), "r"(a[3]), "r"(b0), "r"(b1));
}
__device__ __forceinline__ float elu(float v) {
    return v > 0.f ? v : (__expf(v) - 1.f);
}

__device__ __forceinline__ void fetch_stage(uint32_t wbase, int buf,
                                            const __half* gsrc, int s, int tid) {
    const char* src0 = (const char*)gsrc + (size_t)s * W_STAGE_GB;
    #pragma unroll
    for (int e = 0; e < 2; e++) {
        int id = tid * 2 + e;                 // 0..1023
        int row = id >> 3, i = id & 7;
        uint32_t dst = wbase + buf * WBUF_STAGE_B + row * W_ROW_B + i * 16;
        CP_ASYNC16(dst, src0 + row * 128 + i * 16);
    }
}

__global__ __launch_bounds__(THREADS, 1)
void paiconv_mma(const float* __restrict__ x, const int* __restrict__ idxg,
                 const float* __restrict__ P, const float* __restrict__ b_conv,
                 const float* __restrict__ b_skip, float* __restrict__ out)
{
    extern __shared__ char smem[];
    const uint32_t sb = smem_u32(smem);
    const int tid  = threadIdx.x;
    const int lane = tid & 31;
    const int wid  = tid >> 5;
    const int n0   = blockIdx.x * TM;
    const int b    = blockIdx.y;

    int*   s_idx  = (int*)(smem + IDX_OFF);
    float* s_P    = (float*)(smem + P_OFF);
    float* s_bias = (float*)(smem + BIAS_OFF);

    // ---- stage indices / P / bias ----
    for (int t = tid; t < TM * KK; t += THREADS) s_idx[t] = idxg[n0 * KK + t];
    for (int t = tid; t < TM * 81; t += THREADS) {
        int node = t / 81;
        s_P[node * 84 + (t - node * 81)] = P[(size_t)n0 * 81 + t];
    }
    if (tid < CC)  s_bias[tid] = b_conv[tid];
    else if (tid < 2 * CC) s_bias[tid] = b_skip[tid - CC];
    __syncthreads();

    // prefetch first two W stages (overlaps gather + mix)
    fetch_stage(sb + W_OFF, 0, g_Wc2, 0, tid); CP_COMMIT();
    fetch_stage(sb + W_OFF, 1, g_Wc2, 1, tid); CP_COMMIT();

    const float* xb = x + (size_t)b * NN * CC;

    // ---- gather: 9 neighbor rows -> fp16 flat buffer ----
    for (int t = tid; t < TM * KK * 16; t += THREADS) {
        int row = t >> 4, q = t & 15;          // row = node*9 + j
        int node = row / 9, j = row - node * 9;
        int ix = s_idx[row];
        const float* src = xb + (size_t)ix * CC + q * 8;
        float4 v0 = __ldg((const float4*)src);
        float4 v1 = __ldg((const float4*)(src + 4));
        __half2 h0 = __floats2half2_rn(v0.x, v0.y);
        __half2 h1 = __floats2half2_rn(v0.z, v0.w);
        __half2 h2 = __floats2half2_rn(v1.x, v1.y);
        __half2 h3 = __floats2half2_rn(v1.z, v1.w);
        uint4 u;
        u.x = *(uint32_t*)&h0; u.y = *(uint32_t*)&h1;
        u.z = *(uint32_t*)&h2; u.w = *(uint32_t*)&h3;
        *(uint4*)(smem + FLAT_OFF + node * FLAT_STRIDE_B + j * 256 + q * 16) = u;
    }
    __syncthreads();

    // ---- in-place 9x9 mix + ELU (fp32 math, half2 I/O) ----
    {
        const int node = tid >> 3;
        const int cg   = tid & 7;
        float pr[81];
        const float4* prs = (const float4*)(s_P + node * 84);
        #pragma unroll
        for (int q = 0; q < 20; q++) {
            float4 f = prs[q];
            pr[q * 4] = f.x; pr[q * 4 + 1] = f.y; pr[q * 4 + 2] = f.z; pr[q * 4 + 3] = f.w;
        }
        pr[80] = ((const float*)prs)[80];
        char* base = smem + FLAT_OFF + node * FLAT_STRIDE_B + cg * 32;
        #pragma unroll
        for (int p = 0; p < 8; p++) {
            float va[9], vb[9];
            #pragma unroll
            for (int j = 0; j < 9; j++) {
                float2 f = __half22float2(*(const __half2*)(base + j * 256 + p * 4));
                va[j] = f.x; vb[j] = f.y;
            }
            #pragma unroll
            for (int k = 0; k < 9; k++) {
                float a = 0.f, c = 0.f;
                #pragma unroll
                for (int j = 0; j < 9; j++) {
                    a = fmaf(pr[k * 9 + j], va[j], a);
                    c = fmaf(pr[k * 9 + j], vb[j], c);
                }
                *(__half2*)(base + k * 256 + p * 4) =
                    __floats2half2_rn(elu(a), elu(c));
            }
        }
    }
    __syncthreads();

    // ---- conv GEMM: 18 stages of K=64, warp tile 16m x 32n ----
    const int m0 = (wid >> 2) * 16;
    const int nb = (wid & 3) * 32;
    const uint32_t a_base = sb + FLAT_OFF + (m0 + (lane & 15)) * FLAT_STRIDE_B
                          + (lane >> 4) * 16;
    const uint32_t b_base0 = sb + W_OFF + (nb + (lane & 15)) * W_ROW_B
                           + (lane >> 4) * 16;

    float acc[16];
    #pragma unroll
    for (int i = 0; i < 16; i++) acc[i] = 0.f;

    for (int s = 0; s < 18; s++) {
        if (s < 17) CP_WAIT(1); else CP_WAIT(0);
        __syncthreads();
        const uint32_t bb = b_base0 + (s & 1) * WBUF_STAGE_B;
        #pragma unroll
        for (int q = 0; q < 4; q++) {
            uint32_t af[4], bf0[4], bf1[4];
            ldsm_x4(af,  a_base + (s * 64 + q * 16) * 2);
            ldsm_x4(bf0, bb + q * 32);
            ldsm_x4(bf1, bb + 16 * W_ROW_B + q * 32);
            mma16816(acc + 0,  af, bf0[0], bf0[2]);
            mma16816(acc + 4,  af, bf0[1], bf0[3]);
            mma16816(acc + 8,  af, bf1[0], bf1[2]);
            mma16816(acc + 12, af, bf1[1], bf1[3]);
        }
        __syncthreads();
        if (s + 2 < 18) { fetch_stage(sb + W_OFF, s & 1, g_Wc2, s + 2, tid); CP_COMMIT(); }
    }

    // ---- skip GEMM: stage x tile (fp16) into flat region, 2 stages ----
    __syncthreads();
    fetch_stage(sb + W_OFF, 0, g_Ws2, 0, tid); CP_COMMIT();
    fetch_stage(sb + W_OFF, 1, g_Ws2, 1, tid); CP_COMMIT();
    for (int t = tid; t < TM * 16; t += THREADS) {
        int node = t >> 4, q = t & 15;
        const float* src = xb + (size_t)(n0 + node) * CC + q * 8;
        float4 v0 = __ldg((const float4*)src);
        float4 v1 = __ldg((const float4*)(src + 4));
        __half2 h0 = __floats2half2_rn(v0.x, v0.y);
        __half2 h1 = __floats2half2_rn(v0.z, v0.w);
        __half2 h2 = __floats2half2_rn(v1.x, v1.y);
        __half2 h3 = __floats2half2_rn(v1.z, v1.w);
        uint4 u;
        u.x = *(uint32_t*)&h0; u.y = *(uint32_t*)&h1;
        u.z = *(uint32_t*)&h2; u.w = *(uint32_t*)&h3;
        *(uint4*)(smem + FLAT_OFF + node * XS_STRIDE_B + q * 16) = u;
    }
    CP_WAIT(0);
    __syncthreads();

    float acc2[16];
    #pragma unroll
    for (int i = 0; i < 16; i++) acc2[i] = 0.f;
    const uint32_t a2_base = sb + FLAT_OFF + (m0 + (lane & 15)) * XS_STRIDE_B
                           + (lane >> 4) * 16;
    #pragma unroll
    for (int s = 0; s < 2; s++) {
        const uint32_t bb = b_base0 + s * WBUF_STAGE_B;
        #pragma unroll
        for (int q = 0; q < 4; q++) {
            uint32_t af[4], bf0[4], bf1[4];
            ldsm_x4(af,  a2_base + (s * 64 + q * 16) * 2);
            ldsm_x4(bf0, bb + q * 32);
            ldsm_x4(bf1, bb + 16 * W_ROW_B + q * 32);
            mma16816(acc2 + 0,  af, bf0[0], bf0[2]);
            mma16816(acc2 + 4,  af, bf0[1], bf0[3]);
            mma16816(acc2 + 8,  af, bf1[0], bf1[2]);
            mma16816(acc2 + 12, af, bf1[1], bf1[3]);
        }
    }

    // ---- epilogue: out = elu(Dc + bc) + Ds + bs ----
    #pragma unroll
    for (int t = 0; t < 4; t++) {
        int colp = nb + t * 8 + (lane & 3) * 2;
        float bcx = s_bias[colp],       bcy = s_bias[colp + 1];
        float bsx = s_bias[128 + colp], bsy = s_bias[128 + colp + 1];
        #pragma unroll
        for (int h = 0; h < 2; h++) {
            int r = m0 + (lane >> 2) + h * 8;
            int e = t * 4 + h * 2;
            float2 o2;
            o2.x = elu(acc[e]     + bcx) + acc2[e]     + bsx;
            o2.y = elu(acc[e + 1] + bcy) + acc2[e + 1] + bsy;
            *(float2*)(out + ((size_t)b * NN + n0 + r) * CC + colp) = o2;
        }
    }
}

extern "C" void kernel_launch(void* const* d_in, const int* in_sizes, int n_in,
                              void* d_out, int out_size) {
    const float* x       = (const float*)d_in[0];
    const int*   indices = (const int*)  d_in[1];
    const float* P       = (const float*)d_in[2];
    const float* W_conv  = (const float*)d_in[3];
    const float* b_conv  = (const float*)d_in[4];
    const float* W_skip  = (const float*)d_in[5];
    const float* b_skip  = (const float*)d_in[6];
    float* out = (float*)d_out;

    prep_w<<<(18 * 128 * 64 + 255) / 256, 256>>>(W_conv, W_skip);

    cudaFuncSetAttribute(paiconv_mma,
                         cudaFuncAttributeMaxDynamicSharedMemorySize, SMEM_TOTAL);
    dim3 grid(NN / TM, BB);
    paiconv_mma<<<grid, THREADS, SMEM_TOTAL>>>(x, indices, P, b_conv, b_skip, out);
}

// round 5
// speedup vs baseline: 4.8726x; 1.1063x over previous
#include <cuda_runtime.h>
#include <cuda_fp16.h>
#include <cstdint>

#define BB 16
#define NN 16384
#define CC 128
#define KK 9
#define TM 32
#define THREADS 256
#define NSTAGES 36              // conv K stages of 32

#define FLAT_STRIDE_B 2320      // 1160 halfs (1152 + 8 pad)
#define XS_STRIDE_B   272       // 136 halfs (128 + 8 pad)
#define W_ROW_B       80        // 32 halfs + 8 pad
#define WBUF_STAGE_B  (128 * W_ROW_B)   // 10240
#define W_STAGE_GB    (128 * 32 * 2)    // 8192 bytes per K=32 stage

// smem layout (bytes)
#define FLAT_OFF 0                              // 74240
#define W_OFF    (TM * FLAT_STRIDE_B)           // 74240
#define P_OFF    (W_OFF + 2 * WBUF_STAGE_B)     // 94720 (also xs tile later)
#define XS_OFF   P_OFF
#define IDX_OFF  (P_OFF + TM * 84 * 4)          // 105472
#define BIAS_OFF (IDX_OFF + TM * KK * 4)        // 106624
#define SMEM_TOTAL (BIAS_OFF + 256 * 4)         // 107648

// fp16 pre-transposed weights: conv [36][o128][k32], skip [4][o128][k32]
__device__ __align__(16) __half g_Wc2[NSTAGES * 128 * 32];
__device__ __align__(16) __half g_Ws2[4 * 128 * 32];

__global__ void prep_w(const float* __restrict__ Wc, const float* __restrict__ Ws) {
    int t = blockIdx.x * blockDim.x + threadIdx.x;
    if (t < NSTAGES * 128 * 32) {
        int s = t >> 12, r = t & 4095, o = r >> 5, kk = r & 31;
        g_Wc2[t] = __float2half_rn(Wc[o * 1152 + s * 32 + kk]);
    }
    if (t < 4 * 128 * 32) {
        int s = t >> 12, r = t & 4095, o = r >> 5, kk = r & 31;
        g_Ws2[t] = __float2half_rn(Ws[o * 128 + s * 32 + kk]);
    }
}

// ---------------- PTX helpers (baseline ISA only) ----------------
__device__ __forceinline__ uint32_t smem_u32(const void* p) {
    uint32_t a;
    asm("{ .reg .u64 t; cvta.to.shared.u64 t, %1; cvt.u32.u64 %0, t; }" : "=r"(a) : "l"(p));
    return a;
}
#define CP_ASYNC16(dst, src) \
    asm volatile("cp.async.cg.shared.global [%0], [%1], 16;" :: "r"(dst), "l"(src))
#define CP_COMMIT() asm volatile("cp.async.commit_group;" ::: "memory")
#define CP_WAIT(n)  asm volatile("cp.async.wait_group %0;" :: "n"(n) : "memory")

__device__ __forceinline__ void ldsm_x4(uint32_t* r, uint32_t addr) {
    asm volatile("ldmatrix.sync.aligned.m8n8.x4.shared.b16 {%0,%1,%2,%3}, [%4];"
                 : "=r"(r[0]), "=r"(r[1]), "=r"(r[2]), "=r"(r[3]) : "r"(addr));
}
__device__ __forceinline__ void mma16816(float* c, const uint32_t* a,
                                         uint32_t b0, uint32_t b1) {
    asm volatile("mma.sync.aligned.m16n8k16.row.col.f32.f16.f16.f32 "
                 "{%0,%1,%2,%3}, {%4,%5,%6,%7}, {%8,%9}, {%0,%1,%2,%3};"
                 : "+f"(c[0]), "+f"(c[1]), "+f"(c[2]), "+f"(c[3])
                 : "r"(a[0]), "r"(a[1]), "r"(a[2]), "r"(a[3]), "r"(b0), "r"(b1));
}
__device__ __forceinline__ float elu(float v) {
    return v > 0.f ? v : (__expf(v) - 1.f);
}

__device__ __forceinline__ void fetch_stage(uint32_t wbase, int buf,
                                            const __half* gsrc, int s, int tid) {
    const char* src0 = (const char*)gsrc + (size_t)s * W_STAGE_GB;
    #pragma unroll
    for (int e = 0; e < 2; e++) {
        int id = tid + e * THREADS;            // 0..511
        uint32_t dst = wbase + buf * WBUF_STAGE_B + (id >> 2) * W_ROW_B + (id & 3) * 16;
        CP_ASYNC16(dst, src0 + id * 16);
    }
}

__global__ __launch_bounds__(THREADS, 2)
void paiconv_mma(const float* __restrict__ x, const int* __restrict__ idxg,
                 const float* __restrict__ P, const float* __restrict__ b_conv,
                 const float* __restrict__ b_skip, float* __restrict__ out)
{
    extern __shared__ char smem[];
    const uint32_t sb = smem_u32(smem);
    const int tid  = threadIdx.x;
    const int lane = tid & 31;
    const int wid  = tid >> 5;
    const int n0   = blockIdx.x * TM;
    const int b    = blockIdx.y;

    int*   s_idx  = (int*)(smem + IDX_OFF);
    float* s_P    = (float*)(smem + P_OFF);
    float* s_bias = (float*)(smem + BIAS_OFF);

    // prefetch first two W stages immediately (overlaps staging + mix)
    fetch_stage(sb + W_OFF, 0, g_Wc2, 0, tid); CP_COMMIT();
    fetch_stage(sb + W_OFF, 1, g_Wc2, 1, tid); CP_COMMIT();

    // ---- stage indices / P / bias ----
    for (int t = tid; t < TM * KK; t += THREADS) s_idx[t] = idxg[n0 * KK + t];
    for (int t = tid; t < TM * 81; t += THREADS) {
        int node = t / 81;
        s_P[node * 84 + (t - node * 81)] = P[(size_t)n0 * 81 + t];
    }
    if (tid < CC)  s_bias[tid] = b_conv[tid];
    else           s_bias[tid] = b_skip[tid - CC];
    __syncthreads();

    const float* xb = x + (size_t)b * NN * CC;

    // ---- fused gather + 9x9 mix + ELU -> fp16 flat (fp32 math throughout) ----
    {
        const int node = tid >> 3;
        const int cg   = tid & 7;
        float pr[81];
        const float4* prs = (const float4*)(s_P + node * 84);
        #pragma unroll
        for (int q = 0; q < 20; q++) {
            float4 f = prs[q];
            pr[q * 4] = f.x; pr[q * 4 + 1] = f.y; pr[q * 4 + 2] = f.z; pr[q * 4 + 3] = f.w;
        }
        pr[80] = ((const float*)prs)[80];
        int ixs[KK];
        #pragma unroll
        for (int j = 0; j < KK; j++) ixs[j] = s_idx[node * KK + j];
        char* flat_base = smem + FLAT_OFF + node * FLAT_STRIDE_B + cg * 4;
        #pragma unroll
        for (int p = 0; p < 8; p++) {
            float2 vab[KK];
            #pragma unroll
            for (int j = 0; j < KK; j++)
                vab[j] = __ldg((const float2*)(xb + (size_t)ixs[j] * CC + p * 16 + cg * 2));
            #pragma unroll
            for (int k = 0; k < KK; k++) {
                float a = 0.f, c = 0.f;
                #pragma unroll
                for (int j = 0; j < KK; j++) {
                    a = fmaf(pr[k * 9 + j], vab[j].x, a);
                    c = fmaf(pr[k * 9 + j], vab[j].y, c);
                }
                *(__half2*)(flat_base + k * 256 + p * 32) =
                    __floats2half2_rn(elu(a), elu(c));
            }
        }
    }
    __syncthreads();

    // ---- conv GEMM: 36 stages of K=32, 8 warps, warp tile 16m x 32n ----
    const int m0 = (wid >> 2) * 16;
    const int nb = (wid & 3) * 32;
    const uint32_t a_base = sb + FLAT_OFF + (m0 + (lane & 15)) * FLAT_STRIDE_B
                          + (lane >> 4) * 16;
    const uint32_t b_base0 = sb + W_OFF + (nb + (lane & 15)) * W_ROW_B
                           + (lane >> 4) * 16;

    float acc[16];
    #pragma unroll
    for (int i = 0; i < 16; i++) acc[i] = 0.f;

    for (int s = 0; s < NSTAGES; s++) {
        if (s < NSTAGES - 1) CP_WAIT(1); else CP_WAIT(0);
        __syncthreads();
        const uint32_t bb = b_base0 + (s & 1) * WBUF_STAGE_B;
        #pragma unroll
        for (int q = 0; q < 2; q++) {
            uint32_t af[4], bf0[4], bf1[4];
            ldsm_x4(af,  a_base + s * 64 + q * 32);
            ldsm_x4(bf0, bb + q * 32);
            ldsm_x4(bf1, bb + 16 * W_ROW_B + q * 32);
            mma16816(acc + 0,  af, bf0[0], bf0[2]);
            mma16816(acc + 4,  af, bf0[1], bf0[3]);
            mma16816(acc + 8,  af, bf1[0], bf1[2]);
            mma16816(acc + 12, af, bf1[1], bf1[3]);
        }
        __syncthreads();
        if (s + 2 < NSTAGES) { fetch_stage(sb + W_OFF, s & 1, g_Wc2, s + 2, tid); CP_COMMIT(); }
    }

    // ---- skip GEMM: x (fp16) @ W_skip, 4 stages of K=32 ----
    fetch_stage(sb + W_OFF, 0, g_Ws2, 0, tid); CP_COMMIT();
    fetch_stage(sb + W_OFF, 1, g_Ws2, 1, tid); CP_COMMIT();
    // xs tile overlays the (dead) P region
    for (int t = tid; t < TM * 32; t += THREADS) {
        int node = t >> 5, q = t & 31;
        float4 v = __ldg((const float4*)(xb + (size_t)(n0 + node) * CC + q * 4));
        __half2 h0 = __floats2half2_rn(v.x, v.y);
        __half2 h1 = __floats2half2_rn(v.z, v.w);
        uint2 u;
        u.x = *(uint32_t*)&h0; u.y = *(uint32_t*)&h1;
        *(uint2*)(smem + XS_OFF + node * XS_STRIDE_B + q * 8) = u;
    }
    CP_WAIT(0);
    __syncthreads();

    float acc2[16];
    #pragma unroll
    for (int i = 0; i < 16; i++) acc2[i] = 0.f;
    const uint32_t a2_base = sb + XS_OFF + (m0 + (lane & 15)) * XS_STRIDE_B
                           + (lane >> 4) * 16;

    #pragma unroll
    for (int grp = 0; grp < 2; grp++) {
        #pragma unroll
        for (int sl = 0; sl < 2; sl++) {
            int s = grp * 2 + sl;
            const uint32_t bb = b_base0 + sl * WBUF_STAGE_B;
            #pragma unroll
            for (int q = 0; q < 2; q++) {
                uint32_t af[4], bf0[4], bf1[4];
                ldsm_x4(af,  a2_base + s * 64 + q * 32);
                ldsm_x4(bf0, bb + q * 32);
                ldsm_x4(bf1, bb + 16 * W_ROW_B + q * 32);
                mma16816(acc2 + 0,  af, bf0[0], bf0[2]);
                mma16816(acc2 + 4,  af, bf0[1], bf0[3]);
                mma16816(acc2 + 8,  af, bf1[0], bf1[2]);
                mma16816(acc2 + 12, af, bf1[1], bf1[3]);
            }
        }
        if (grp == 0) {
            __syncthreads();
            fetch_stage(sb + W_OFF, 0, g_Ws2, 2, tid); CP_COMMIT();
            fetch_stage(sb + W_OFF, 1, g_Ws2, 3, tid); CP_COMMIT();
            CP_WAIT(0);
            __syncthreads();
        }
    }

    // ---- epilogue: out = elu(Dc + bc) + Ds + bs ----
    #pragma unroll
    for (int t = 0; t < 4; t++) {
        int colp = nb + t * 8 + (lane & 3) * 2;
        float bcx = s_bias[colp],       bcy = s_bias[colp + 1];
        float bsx = s_bias[128 + colp], bsy = s_bias[128 + colp + 1];
        #pragma unroll
        for (int h = 0; h < 2; h++) {
            int r = m0 + (lane >> 2) + h * 8;
            int e = t * 4 + h * 2;
            float2 o2;
            o2.x = elu(acc[e]     + bcx) + acc2[e]     + bsx;
            o2.y = elu(acc[e + 1] + bcy) + acc2[e + 1] + bsy;
            *(float2*)(out + ((size_t)b * NN + n0 + r) * CC + colp) = o2;
        }
    }
}

extern "C" void kernel_launch(void* const* d_in, const int* in_sizes, int n_in,
                              void* d_out, int out_size) {
    const float* x       = (const float*)d_in[0];
    const int*   indices = (const int*)  d_in[1];
    const float* P       = (const float*)d_in[2];
    const float* W_conv  = (const float*)d_in[3];
    const float* b_conv  = (const float*)d_in[4];
    const float* W_skip  = (const float*)d_in[5];
    const float* b_skip  = (const float*)d_in[6];
    float* out = (float*)d_out;

    prep_w<<<(NSTAGES * 128 * 32 + 255) / 256, 256>>>(W_conv, W_skip);

    cudaFuncSetAttribute(paiconv_mma,
                         cudaFuncAttributeMaxDynamicSharedMemorySize, SMEM_TOTAL);
    dim3 grid(NN / TM, BB);
    paiconv_mma<<<grid, THREADS, SMEM_TOTAL>>>(x, indices, P, b_conv, b_skip, out);
}

// round 6
// speedup vs baseline: 6.3079x; 1.2946x over previous
#include <cuda_runtime.h>
#include <cuda_fp16.h>
#include <cstdint>

#define BB 16
#define NN 16384
#define CC 128
#define KK 9
#define TM 128
#define THREADS 256
#define NCHUNK_CONV 72          // 8 c8 * 9 ko, K=16 each
#define NCHUNK 80               // + 8 skip chunks
#define CHUNK_HALVES 2048       // 128 o-rows * 16 k
#define CHUNK_GB 4096           // bytes in global
#define W_ROW_SB 48             // smem row stride (32B data + 16B pad)
#define WBUF_B (128 * W_ROW_SB) // 6144
#define NBUF 4

// smem layout (bytes)
#define WBUF_OFF 0                          // 4 * 6144 = 24576
#define P2_OFF   (NBUF * WBUF_B)            // 24576, 128*9*12*4 = 55296
#define IDX_OFF  (P2_OFF + 55296)           // 79872, 128*9*4 = 4608
#define BIAS_OFF (IDX_OFF + 4608)           // 84480, 256*4
#define SMEM_TOTAL (BIAS_OFF + 1024)        // 85504

// W pre-permuted fp16: [chunk][o(128)][p(16)]
__device__ __align__(16) __half g_Wc[NCHUNK_CONV * CHUNK_HALVES];
__device__ __align__(16) __half g_Ws[8 * CHUNK_HALVES];

// position p -> channel-within-16 (so lane's 4 frag k-values are contiguous)
__host__ __device__ __forceinline__ int perm16(int p) {
    int e = p & 1;
    return (p < 8) ? ((p >> 1) * 4 + e) : (((p - 8) >> 1) * 4 + 2 + e);
}

__global__ void prep_w(const float* __restrict__ Wc, const float* __restrict__ Ws) {
    int t = blockIdx.x * blockDim.x + threadIdx.x;
    if (t < NCHUNK_CONV * CHUNK_HALVES) {
        int q = t >> 11, r = t & 2047, o = r >> 4, p = r & 15;
        int c8 = q / 9, ko = q % 9;
        int f = ko * CC + c8 * 16 + perm16(p);
        g_Wc[t] = __float2half_rn(Wc[o * 1152 + f]);
    }
    if (t < 8 * CHUNK_HALVES) {
        int q = t >> 11, r = t & 2047, o = r >> 4, p = r & 15;
        g_Ws[t] = __float2half_rn(Ws[o * CC + q * 16 + perm16(p)]);
    }
}

// ---------------- PTX helpers ----------------
__device__ __forceinline__ uint32_t smem_u32(const void* p) {
    uint32_t a;
    asm("{ .reg .u64 t; cvta.to.shared.u64 t, %1; cvt.u32.u64 %0, t; }" : "=r"(a) : "l"(p));
    return a;
}
#define CP_ASYNC16(dst, src) \
    asm volatile("cp.async.cg.shared.global [%0], [%1], 16;" :: "r"(dst), "l"(src))
#define CP_COMMIT() asm volatile("cp.async.commit_group;" ::: "memory")
#define CP_WAIT(n)  asm volatile("cp.async.wait_group %0;" :: "n"(n) : "memory")

__device__ __forceinline__ void ldsm_x4(uint32_t* r, uint32_t addr) {
    asm volatile("ldmatrix.sync.aligned.m8n8.x4.shared.b16 {%0,%1,%2,%3}, [%4];"
                 : "=r"(r[0]), "=r"(r[1]), "=r"(r[2]), "=r"(r[3]) : "r"(addr));
}
__device__ __forceinline__ void mma16816(float* c, const uint32_t* a,
                                         uint32_t b0, uint32_t b1) {
    asm volatile("mma.sync.aligned.m16n8k16.row.col.f32.f16.f16.f32 "
                 "{%0,%1,%2,%3}, {%4,%5,%6,%7}, {%8,%9}, {%0,%1,%2,%3};"
                 : "+f"(c[0]), "+f"(c[1]), "+f"(c[2]), "+f"(c[3])
                 : "r"(a[0]), "r"(a[1]), "r"(a[2]), "r"(a[3]), "r"(b0), "r"(b1));
}
__device__ __forceinline__ float elu(float v) {
    float e;
    asm("ex2.approx.f32 %0, %1;" : "=f"(e) : "f"(v * 1.44269504f));
    return v > 0.f ? v : e - 1.f;
}
__device__ __forceinline__ void fma4(float4& a, float s, const float4& v) {
    a.x = fmaf(s, v.x, a.x); a.y = fmaf(s, v.y, a.y);
    a.z = fmaf(s, v.z, a.z); a.w = fmaf(s, v.w, a.w);
}
__device__ __forceinline__ uint32_t h2pack(float a, float b) {
    __half2 h = __floats2half2_rn(a, b);
    return *reinterpret_cast<uint32_t*>(&h);
}

// cooperative chunk fetch: 256 threads, 2 x 16B rows each handles half a row
__device__ __forceinline__ void issue_chunk(uint32_t wbase, int i, int tid) {
    const char* src = (i < NCHUNK_CONV)
        ? (const char*)g_Wc + (size_t)i * CHUNK_GB
        : (const char*)g_Ws + (size_t)(i - NCHUNK_CONV) * CHUNK_GB;
    int o = tid >> 1, h = tid & 1;
    uint32_t dst = wbase + (i & (NBUF - 1)) * WBUF_B + o * W_ROW_SB + h * 16;
    CP_ASYNC16(dst, src + o * 32 + h * 16);
    CP_COMMIT();
}

__global__ __launch_bounds__(THREADS, 1)
void paiconv_rf(const float* __restrict__ x, const int* __restrict__ idxg,
                const float* __restrict__ P, const float* __restrict__ b_conv,
                const float* __restrict__ b_skip, float* __restrict__ out)
{
    extern __shared__ char smem[];
    const uint32_t sb = smem_u32(smem);
    const int tid  = threadIdx.x;
    const int lane = tid & 31;
    const int wid  = tid >> 5;
    const int n0   = blockIdx.x * TM;
    const int b    = blockIdx.y;

    float* s_P2   = (float*)(smem + P2_OFF);     // [node][ko][12]
    int*   s_idx  = (int*)(smem + IDX_OFF);
    float* s_bias = (float*)(smem + BIAS_OFF);

    // start W pipeline immediately
    issue_chunk(sb + WBUF_OFF, 0, tid);
    issue_chunk(sb + WBUF_OFF, 1, tid);
    issue_chunk(sb + WBUF_OFF, 2, tid);

    // stage P (padded [node][ko][12]), idx, bias
    for (int t = tid; t < TM * 81; t += THREADS) {
        int node = t / 81, rem = t - node * 81;
        int ko = rem / 9, j = rem - ko * 9;
        s_P2[node * 108 + ko * 12 + j] = P[(size_t)n0 * 81 + t];
    }
    for (int t = tid; t < TM * KK; t += THREADS) s_idx[t] = idxg[n0 * KK + t];
    if (tid < CC)  s_bias[tid] = b_conv[tid];
    else           s_bias[tid] = b_skip[tid - CC];
    __syncthreads();

    const float* xb = x + (size_t)b * NN * CC;

    // lane-owned rows within warp m16 tile
    const int r0l = wid * 16 + (lane >> 2);      // local node 0..127
    const int r1l = r0l + 8;
    const int q4  = (lane & 3) * 16;             // byte offset of lane's float4

    // cache neighbor indices for both rows
    int idxr[2][KK];
    #pragma unroll
    for (int j = 0; j < KK; j++) {
        idxr[0][j] = s_idx[r0l * KK + j];
        idxr[1][j] = s_idx[r1l * KK + j];
    }

    float acc[64];
    #pragma unroll
    for (int i = 0; i < 64; i++) acc[i] = 0.f;

    float4 xg[2][KK];
    const uint32_t ldsm_base = sb + WBUF_OFF + (lane & 15) * W_ROW_SB + (lane >> 4) * 16;

    // ---------------- conv: 72 chunks (c8 outer, ko inner) ----------------
    int ci = 0;
    for (int c8 = 0; c8 < 8; c8++) {
        // gather this channel-slice for 2 rows x 9 neighbors (reused for 9 ko)
        #pragma unroll
        for (int r = 0; r < 2; r++)
            #pragma unroll
            for (int j = 0; j < KK; j++) {
                int ix = idxr[r][j];
                float4 v = make_float4(0.f, 0.f, 0.f, 0.f);
                if ((unsigned)ix < (unsigned)NN)
                    v = __ldg((const float4*)((const char*)xb + (size_t)ix * 512 + c8 * 64 + q4));
                xg[r][j] = v;
            }
        #pragma unroll
        for (int ko = 0; ko < 9; ko++, ci++) {
            if (ci < 78) CP_WAIT(2); else if (ci == 78) CP_WAIT(1); else CP_WAIT(0);
            __syncthreads();
            if (ci + 3 < NCHUNK) issue_chunk(sb + WBUF_OFF, ci + 3, tid);

            // mix: v0/v1 = P[row][ko][:] . xg[row][:]  (fp32)
            const float* p0 = s_P2 + r0l * 108 + ko * 12;
            const float* p1 = s_P2 + r1l * 108 + ko * 12;
            float4 v0 = make_float4(0.f, 0.f, 0.f, 0.f);
            float4 v1 = make_float4(0.f, 0.f, 0.f, 0.f);
            float4 pa0 = *(const float4*)p0, pb0 = *(const float4*)(p0 + 4);
            float4 pa1 = *(const float4*)p1, pb1 = *(const float4*)(p1 + 4);
            fma4(v0, pa0.x, xg[0][0]); fma4(v0, pa0.y, xg[0][1]);
            fma4(v0, pa0.z, xg[0][2]); fma4(v0, pa0.w, xg[0][3]);
            fma4(v0, pb0.x, xg[0][4]); fma4(v0, pb0.y, xg[0][5]);
            fma4(v0, pb0.z, xg[0][6]); fma4(v0, pb0.w, xg[0][7]);
            fma4(v0, p0[8], xg[0][8]);
            fma4(v1, pa1.x, xg[1][0]); fma4(v1, pa1.y, xg[1][1]);
            fma4(v1, pa1.z, xg[1][2]); fma4(v1, pa1.w, xg[1][3]);
            fma4(v1, pb1.x, xg[1][4]); fma4(v1, pb1.y, xg[1][5]);
            fma4(v1, pb1.z, xg[1][6]); fma4(v1, pb1.w, xg[1][7]);
            fma4(v1, p1[8], xg[1][8]);

            uint32_t a[4];
            a[0] = h2pack(elu(v0.x), elu(v0.y));
            a[1] = h2pack(elu(v1.x), elu(v1.y));
            a[2] = h2pack(elu(v0.z), elu(v0.w));
            a[3] = h2pack(elu(v1.z), elu(v1.w));

            const uint32_t wb = ldsm_base + (ci & (NBUF - 1)) * WBUF_B;
            #pragma unroll
            for (int g = 0; g < 8; g++) {
                uint32_t bf[4];
                ldsm_x4(bf, wb + g * 16 * W_ROW_SB);
                mma16816(acc + (2 * g) * 4,     a, bf[0], bf[2]);
                mma16816(acc + (2 * g + 1) * 4, a, bf[1], bf[3]);
            }
        }
    }

    // ---------------- fold: acc = elu(acc + bc) + bs ----------------
    {
        const int cbase = (lane & 3) * 2;
        #pragma unroll
        for (int t = 0; t < 16; t++) {
            int col = t * 8 + cbase;
            float2 bc = *(const float2*)(s_bias + col);
            float2 bs2 = *(const float2*)(s_bias + 128 + col);
            acc[t * 4 + 0] = elu(acc[t * 4 + 0] + bc.x) + bs2.x;
            acc[t * 4 + 1] = elu(acc[t * 4 + 1] + bc.y) + bs2.y;
            acc[t * 4 + 2] = elu(acc[t * 4 + 2] + bc.x) + bs2.x;
            acc[t * 4 + 3] = elu(acc[t * 4 + 3] + bc.y) + bs2.y;
        }
    }

    // ---------------- skip: 8 chunks, A = x directly ----------------
    for (int c8 = 0; c8 < 8; c8++, ci++) {
        if (ci < 78) CP_WAIT(2); else if (ci == 78) CP_WAIT(1); else CP_WAIT(0);
        __syncthreads();
        if (ci + 3 < NCHUNK) issue_chunk(sb + WBUF_OFF, ci + 3, tid);

        float4 v0 = __ldg((const float4*)((const char*)xb + (size_t)(n0 + r0l) * 512 + c8 * 64 + q4));
        float4 v1 = __ldg((const float4*)((const char*)xb + (size_t)(n0 + r1l) * 512 + c8 * 64 + q4));
        uint32_t a[4];
        a[0] = h2pack(v0.x, v0.y);
        a[1] = h2pack(v1.x, v1.y);
        a[2] = h2pack(v0.z, v0.w);
        a[3] = h2pack(v1.z, v1.w);

        const uint32_t wb = ldsm_base + (ci & (NBUF - 1)) * WBUF_B;
        #pragma unroll
        for (int g = 0; g < 8; g++) {
            uint32_t bf[4];
            ldsm_x4(bf, wb + g * 16 * W_ROW_SB);
            mma16816(acc + (2 * g) * 4,     a, bf[0], bf[2]);
            mma16816(acc + (2 * g + 1) * 4, a, bf[1], bf[3]);
        }
    }

    // ---------------- epilogue: store ----------------
    {
        const int cbase = (lane & 3) * 2;
        float* o0 = out + ((size_t)b * NN + n0 + r0l) * CC + cbase;
        float* o1 = out + ((size_t)b * NN + n0 + r1l) * CC + cbase;
        #pragma unroll
        for (int t = 0; t < 16; t++) {
            *(float2*)(o0 + t * 8) = make_float2(acc[t * 4 + 0], acc[t * 4 + 1]);
            *(float2*)(o1 + t * 8) = make_float2(acc[t * 4 + 2], acc[t * 4 + 3]);
        }
    }
}

extern "C" void kernel_launch(void* const* d_in, const int* in_sizes, int n_in,
                              void* d_out, int out_size) {
    const float* x       = (const float*)d_in[0];
    const int*   indices = (const int*)  d_in[1];
    const float* P       = (const float*)d_in[2];
    const float* W_conv  = (const float*)d_in[3];
    const float* b_conv  = (const float*)d_in[4];
    const float* W_skip  = (const float*)d_in[5];
    const float* b_skip  = (const float*)d_in[6];
    float* out = (float*)d_out;

    prep_w<<<(NCHUNK_CONV * CHUNK_HALVES + 255) / 256, 256>>>(W_conv, W_skip);

    cudaFuncSetAttribute(paiconv_rf,
                         cudaFuncAttributeMaxDynamicSharedMemorySize, SMEM_TOTAL);
    dim3 grid(NN / TM, BB);
    paiconv_rf<<<grid, THREADS, SMEM_TOTAL>>>(x, indices, P, b_conv, b_skip, out);
}